// round 3
// baseline (speedup 1.0000x reference)
#include <cuda_runtime.h>
#include <stdint.h>

typedef unsigned long long u64;
typedef unsigned int u32;

#define NLEV 5
#define CLSN 16
#define TOPK 1000
#define NTOT 785664
#define KTOT (NLEV * TOPK)     /* 5000 */
#define ROWS (KTOT * CLSN)     /* 80000 */
#define HBINS 65536
#define WCAP 4096
#define MAXD 4.135166556742356f

__device__ __constant__ int d_off[6] = {0, 589824, 737280, 774144, 783360, 785664};
__device__ __constant__ int d_len[5] = {589824, 147456, 36864, 9216, 2304};

struct Ptrs {
    const float* anc[NLEV];
    const float* cls[NLEV];
    const float* reg[NLEV];
};

// ---------------- scratch (static device globals; no allocation) ----------------
__device__ int g_hist[NLEV * HBINS];   // zeroed by memset node
__device__ int g_nwin[NLEV];           // zeroed by memset node
__device__ u32 g_ord[NTOT];
__device__ u64 g_win[NLEV][WCAP];
__device__ int g_thr[NLEV];

// ---- K1: ruler = max over 16 logits -> ordered key; 16-bit global histogram ----
// 2 anchors per thread: 128B contiguous read per thread, 8 independent float4 loads
__global__ void k_ruler(Ptrs p) {
    int g = blockIdx.x * 256 + threadIdx.x;
#pragma unroll
    for (int q = 0; q < 2; q++) {
        int a = g * 2 + q;
        if (a >= NTOT) return;
        int l = 0;
#pragma unroll
        for (int j = 1; j < NLEV; j++) l += (a >= d_off[j]);
        int i = a - d_off[l];

        const float4* c4 = (const float4*)(p.cls[l]) + (size_t)i * 4;
        float4 va = c4[0], vb = c4[1], vc = c4[2], vd = c4[3];
        float m = fmaxf(fmaxf(fmaxf(va.x, va.y), fmaxf(va.z, va.w)),
                        fmaxf(fmaxf(vb.x, vb.y), fmaxf(vb.z, vb.w)));
        m = fmaxf(m, fmaxf(fmaxf(vc.x, vc.y), fmaxf(vc.z, vc.w)));
        m = fmaxf(m, fmaxf(fmaxf(vd.x, vd.y), fmaxf(vd.z, vd.w)));

        u32 u = __float_as_uint(m);
        u32 ord = (u & 0x80000000u) ? ~u : (u | 0x80000000u);  // monotonic
        g_ord[a] = ord;

        // warp-aggregated histogram add, keyed on (level, bin)
        u32 key = (u32)l * HBINS + (ord >> 16);
        unsigned act = __activemask();
        unsigned peers = __match_any_sync(act, key);
        if ((peers & ((1u << (threadIdx.x & 31)) - 1)) == 0)   // lowest lane in group
            atomicAdd(&g_hist[key], __popc(peers));
    }
}

// ---- K2: per-level threshold bin: largest T with suffix_count(T) >= TOPK ----
__global__ void k_resolve() {
    int l = blockIdx.x;
    int t = threadIdx.x;               // 1024 threads
    const int CH = HBINS / 1024;       // 64 bins per thread
    __shared__ int csum[1024];
    __shared__ int s_cidx, s_sufnext;
    __shared__ int s_bins[64];

    const int* h = &g_hist[l * HBINS];
    int base = t * CH, s = 0;
#pragma unroll 4
    for (int j = 0; j < CH; j++) s += h[base + j];
    csum[t] = s;
    __syncthreads();
    for (int off = 1; off < 1024; off <<= 1) {   // reversed Hillis-Steele suffix sum
        int v = csum[t];
        int add = (t + off < 1024) ? csum[t + off] : 0;
        __syncthreads();
        csum[t] = v + add;
        __syncthreads();
    }
    if (csum[t] >= TOPK && (t == 1023 || csum[t + 1] < TOPK)) {
        s_cidx = t;
        s_sufnext = (t == 1023) ? 0 : csum[t + 1];
    }
    __syncthreads();
    int cbase = s_cidx * CH;
    if (t < CH) s_bins[t] = h[cbase + t];
    __syncthreads();
    if (t == 0) {
        int suf = s_sufnext, b = cbase + CH - 1;
        for (int j = CH - 1; j >= 0; j--) {
            suf += s_bins[j];
            b = cbase + j;
            if (suf >= TOPK) break;
        }
        g_thr[l] = b;
    }
}

// ---- K3: collect every key with top16 >= threshold (ballot-aggregated) ----
__global__ void k_select() {
    int g = blockIdx.x * 256 + threadIdx.x;
#pragma unroll
    for (int q = 0; q < 2; q++) {
        int a = g * 2 + q;
        bool ok = (a < NTOT);
        int l = 0;
        u32 ord = 0;
        if (ok) {
            ord = g_ord[a];
#pragma unroll
            for (int j = 1; j < NLEV; j++) l += (a >= d_off[j]);
        }
        bool win = ok && (ord >> 16) >= (u32)g_thr[l];
        unsigned act = __activemask();
        unsigned mask = __ballot_sync(act, win);
        if (win) {
            // sub-group by level (blocks can straddle levels at boundaries)
            unsigned lvmask = __match_any_sync(act, win ? l : -1) & mask;
            int lane = threadIdx.x & 31;
            int leader = __ffs(lvmask) - 1;
            int rank = __popc(lvmask & ((1u << lane) - 1));
            int base = 0;
            if (lane == leader) base = atomicAdd(&g_nwin[l], __popc(lvmask));
            base = __shfl_sync(lvmask, base, leader);
            int w = base + rank;
            if (w < WCAP) g_win[l][w] = ((u64)ord << 32) | (u32)(a - d_off[l]);
        }
    }
}

// ---- K4: exact rank (value desc, idx asc) + decode + emit output rows ----
__global__ void k_rank_final(Ptrs p, float* __restrict__ out) {
    __shared__ u64 s[WCAP];
    __shared__ u32 sel[TOPK];
    __shared__ float4 bbox[TOPK];
    int l = blockIdx.x;
    int n = g_nwin[l];
    if (n > WCAP) n = WCAP;
    int t = threadIdx.x;               // 1024 threads
    for (int i = t; i < n; i += 1024)
        s[i] = g_win[l][i] ^ 0xFFFFFFFF00000000ULL;  // ascending (~ord, idx)
    __syncthreads();
    for (int i = t; i < n; i += 1024) {
        u64 me = s[i];
        int rank = 0;
        int j = 0;
        for (; j + 4 <= n; j += 4)
            rank += (s[j] < me) + (s[j + 1] < me) + (s[j + 2] < me) + (s[j + 3] < me);
        for (; j < n; j++) rank += (s[j] < me);
        if (rank < TOPK) sel[rank] = (u32)(me & 0xFFFFFFFFu);
    }
    __syncthreads();

    // decode 1000 boxes into smem
    if (t < TOPK) {
        u32 idx = sel[t];
        if (idx >= (u32)d_len[l]) idx = 0;  // safety
        float4 a4 = ((const float4*)p.anc[l])[idx];
        float4 r4 = ((const float4*)p.reg[l])[idx * 2];
        float w = a4.z - a4.x, h = a4.w - a4.y;
        float cx = a4.x + 0.5f * w, cy = a4.y + 0.5f * h;
        float pcx = cx + r4.x * w, pcy = cy + r4.y * h;
        float pw = w * expf(fminf(r4.z, MAXD));
        float ph = h * expf(fminf(r4.w, MAXD));
        bbox[t] = make_float4(pcx - 0.5f * pw, pcy - 0.5f * ph,
                              pcx + 0.5f * pw, pcy + 0.5f * ph);
    }
    __syncthreads();

    // emit 16000 rows for this level
    const float* cls = p.cls[l];
    for (int r0 = t; r0 < TOPK * CLSN; r0 += 1024) {
        int k = r0 >> 4;
        int c = r0 & 15;
        u32 idx = sel[k];
        if (idx >= (u32)d_len[l]) idx = 0;
        float score = cls[(size_t)idx * 16 + c];
        float sg = 1.0f / (1.0f + expf(-score));
        float4 b4 = bbox[k];
        float* o = out + ((size_t)(l * TOPK + k) * CLSN + c) * 6;
        o[0] = b4.x;
        o[1] = b4.y;
        o[2] = b4.z;
        o[3] = b4.w;
        o[4] = sg;
        o[5] = (float)(c + 1);
    }
}

extern "C" void kernel_launch(void* const* d_in, const int* in_sizes, int n_in,
                              void* d_out, int out_size) {
    (void)in_sizes; (void)n_in; (void)out_size;
    Ptrs p;
    for (int l = 0; l < NLEV; l++) {
        p.anc[l] = (const float*)d_in[3 * l + 0];
        p.cls[l] = (const float*)d_in[3 * l + 1];
        p.reg[l] = (const float*)d_in[3 * l + 2];
    }

    void* hist_ptr = nullptr;
    void* nwin_ptr = nullptr;
    cudaGetSymbolAddress(&hist_ptr, g_hist);
    cudaGetSymbolAddress(&nwin_ptr, g_nwin);
    cudaMemsetAsync(hist_ptr, 0, (size_t)NLEV * HBINS * sizeof(int), 0);
    cudaMemsetAsync(nwin_ptr, 0, (size_t)NLEV * sizeof(int), 0);

    const int g2 = (NTOT + 511) / 512;   // 2 elements/thread
    k_ruler<<<g2, 256>>>(p);
    k_resolve<<<NLEV, 1024>>>();
    k_select<<<g2, 256>>>();
    k_rank_final<<<NLEV, 1024>>>(p, (float*)d_out);
}

// round 4
// speedup vs baseline: 1.0319x; 1.0319x over previous
#include <cuda_runtime.h>
#include <stdint.h>

typedef unsigned long long u64;
typedef unsigned int u32;

#define NLEV 5
#define CLSN 16
#define TOPK 1000
#define NTOT 785664
#define HBINS 65536
#define WCAP 2048
#define MAXD 4.135166556742356f

__device__ __constant__ int d_off[6] = {0, 589824, 737280, 774144, 783360, 785664};
__device__ __constant__ int d_len[5] = {589824, 147456, 36864, 9216, 2304};

struct Ptrs {
    const float* anc[NLEV];
    const float* cls[NLEV];
    const float* reg[NLEV];
};

// ---------------- scratch (static device globals; no allocation) ----------------
__device__ int g_hist[NLEV * HBINS];
__device__ u32 g_ord[NTOT];
__device__ u64 g_win[NLEV][WCAP];
__device__ int g_nwin[NLEV];
__device__ int g_thr[NLEV];
__device__ int g_barcnt = 0;
__device__ volatile unsigned g_bargen = 0;

// ---------------- grid-wide barrier (all blocks co-resident) ----------------
__device__ __forceinline__ void gridbar(int nblk) {
    __syncthreads();
    if (threadIdx.x == 0) {
        unsigned gen = g_bargen;
        __threadfence();
        if (atomicAdd(&g_barcnt, 1) == nblk - 1) {
            g_barcnt = 0;
            __threadfence();
            g_bargen = gen + 1;
        } else {
            while (g_bargen == gen) __nanosleep(64);
        }
        __threadfence();
    }
    __syncthreads();
}

__global__ void __launch_bounds__(1024, 1)
k_uber(Ptrs p, float* __restrict__ out, int nblk) {
    __shared__ u64 s[WCAP];       // 16KB: sort keys (reused as csum in resolve)
    __shared__ u32 sel[TOPK];     // 4KB
    __shared__ float4 bbox[TOPK]; // 16KB
    __shared__ int s_cidx, s_sufnext, s_bins[64];

    const int t = threadIdx.x;
    const int gt = blockIdx.x * 1024 + t;
    const int gsz = nblk * 1024;
    const int lane = t & 31;

    // ---- P0: zero histograms + counters ----
    for (int i = gt; i < NLEV * HBINS; i += gsz) g_hist[i] = 0;
    if (gt < NLEV) g_nwin[gt] = 0;
    gridbar(nblk);

    // ---- P1: ruler = max of 16 logits -> ordered key + 16-bit histogram ----
    for (int l = 0; l < NLEV; l++) {
        const float4* cls4 = (const float4*)p.cls[l];
        const int n = d_len[l], base = d_off[l];
        for (int i = gt; i < n; i += gsz) {
            float4 va = cls4[i * 4 + 0], vb = cls4[i * 4 + 1];
            float4 vc = cls4[i * 4 + 2], vd = cls4[i * 4 + 3];
            float m = fmaxf(fmaxf(fmaxf(va.x, va.y), fmaxf(va.z, va.w)),
                            fmaxf(fmaxf(vb.x, vb.y), fmaxf(vb.z, vb.w)));
            m = fmaxf(m, fmaxf(fmaxf(vc.x, vc.y), fmaxf(vc.z, vc.w)));
            m = fmaxf(m, fmaxf(fmaxf(vd.x, vd.y), fmaxf(vd.z, vd.w)));
            u32 u = __float_as_uint(m);
            u32 ord = (u & 0x80000000u) ? ~u : (u | 0x80000000u);  // monotonic
            g_ord[base + i] = ord;
            u32 key = (u32)l * HBINS + (ord >> 16);
            unsigned act = __activemask();
            unsigned peers = __match_any_sync(act, key);
            if ((peers & ((1u << lane) - 1)) == 0)
                atomicAdd(&g_hist[key], __popc(peers));
        }
    }
    gridbar(nblk);

    // ---- P2: per-level threshold bin (blocks 0..4) ----
    if (blockIdx.x < NLEV) {
        const int l = blockIdx.x;
        int* csum = (int*)s;
        const int CH = HBINS / 1024;   // 64
        const int* h = &g_hist[l * HBINS];
        int bidx = t * CH, acc = 0;
#pragma unroll 4
        for (int j = 0; j < CH; j++) acc += h[bidx + j];
        csum[t] = acc;
        __syncthreads();
        for (int off = 1; off < 1024; off <<= 1) {  // reversed scan -> suffix sums
            int v = csum[t];
            int add = (t + off < 1024) ? csum[t + off] : 0;
            __syncthreads();
            csum[t] = v + add;
            __syncthreads();
        }
        if (csum[t] >= TOPK && (t == 1023 || csum[t + 1] < TOPK)) {
            s_cidx = t;
            s_sufnext = (t == 1023) ? 0 : csum[t + 1];
        }
        __syncthreads();
        int cbase = s_cidx * CH;
        if (t < CH) s_bins[t] = h[cbase + t];
        __syncthreads();
        if (t == 0) {
            int suf = s_sufnext, b = cbase + CH - 1;
            for (int j = CH - 1; j >= 0; j--) {
                suf += s_bins[j];
                b = cbase + j;
                if (suf >= TOPK) break;
            }
            g_thr[l] = b;
        }
    }
    gridbar(nblk);

    // ---- P3: collect all keys with top16 >= thr (uint4 reads, agg atomics) ----
    for (int l = 0; l < NLEV; l++) {
        const u32 thr = (u32)g_thr[l];
        const int n4 = d_len[l] >> 2, base = d_off[l];
        const uint4* o4 = (const uint4*)&g_ord[base];
        for (int i = gt; i < n4; i += gsz) {
            uint4 v = o4[i];
#pragma unroll
            for (int q = 0; q < 4; q++) {
                u32 ord = (q == 0) ? v.x : (q == 1) ? v.y : (q == 2) ? v.z : v.w;
                if ((ord >> 16) >= thr) {
                    unsigned grp = __activemask();
                    int leader = __ffs(grp) - 1;
                    int rk = __popc(grp & ((1u << lane) - 1));
                    int wbase = 0;
                    if (lane == leader) wbase = atomicAdd(&g_nwin[l], __popc(grp));
                    wbase = __shfl_sync(grp, wbase, leader);
                    int w = wbase + rk;
                    if (w < WCAP)
                        g_win[l][w] = ((u64)ord << 32) | (u32)(i * 4 + q);
                }
            }
        }
    }
    gridbar(nblk);

    // ---- P4: bitonic sort (value desc, idx asc) + decode + emit (blocks 0..4) --
    if (blockIdx.x >= NLEV) return;
    {
        const int l = blockIdx.x;
        int n = g_nwin[l];
        if (n > WCAP) n = WCAP;
        for (int i = t; i < WCAP; i += 1024)
            s[i] = (i < n) ? (g_win[l][i] ^ 0xFFFFFFFF00000000ULL)
                           : 0xFFFFFFFFFFFFFFFFULL;   // ascending (~ord, idx)
        __syncthreads();
        for (int k2 = 2; k2 <= WCAP; k2 <<= 1) {
            for (int j = k2 >> 1; j > 0; j >>= 1) {
                for (int i = t; i < WCAP; i += 1024) {
                    int pr = i ^ j;
                    if (pr > i) {
                        bool up = ((i & k2) == 0);
                        u64 x = s[i], y = s[pr];
                        if ((x > y) == up) { s[i] = y; s[pr] = x; }
                    }
                }
                __syncthreads();
            }
        }
        if (t < TOPK) {
            u32 idx = (u32)(s[t] & 0xFFFFFFFFu);
            if (idx >= (u32)d_len[l]) idx = 0;   // safety (unwritten slots)
            sel[t] = idx;
        }
        __syncthreads();

        // decode 1000 boxes
        if (t < TOPK) {
            u32 idx = sel[t];
            float4 a4 = ((const float4*)p.anc[l])[idx];
            float4 r4 = ((const float4*)p.reg[l])[idx * 2];
            float w = a4.z - a4.x, h = a4.w - a4.y;
            float cx = a4.x + 0.5f * w, cy = a4.y + 0.5f * h;
            float pcx = cx + r4.x * w, pcy = cy + r4.y * h;
            float pw = w * expf(fminf(r4.z, MAXD));
            float ph = h * expf(fminf(r4.w, MAXD));
            bbox[t] = make_float4(pcx - 0.5f * pw, pcy - 0.5f * ph,
                                  pcx + 0.5f * pw, pcy + 0.5f * ph);
        }
        __syncthreads();

        // emit 16000 rows for this level (3 x float2 stores per 24B row)
        const float* cls = p.cls[l];
        float* obase = out + (size_t)l * TOPK * CLSN * 6;
        for (int r0 = t; r0 < TOPK * CLSN; r0 += 1024) {
            int k = r0 >> 4, c = r0 & 15;
            u32 idx = sel[k];
            float score = cls[(size_t)idx * 16 + c];
            float sg = 1.0f / (1.0f + expf(-score));
            float4 b4 = bbox[k];
            float2* o = (float2*)(obase + (size_t)r0 * 6);
            o[0] = make_float2(b4.x, b4.y);
            o[1] = make_float2(b4.z, b4.w);
            o[2] = make_float2(sg, (float)(c + 1));
        }
    }
}

extern "C" void kernel_launch(void* const* d_in, const int* in_sizes, int n_in,
                              void* d_out, int out_size) {
    (void)in_sizes; (void)n_in; (void)out_size;
    Ptrs p;
    for (int l = 0; l < NLEV; l++) {
        p.anc[l] = (const float*)d_in[3 * l + 0];
        p.cls[l] = (const float*)d_in[3 * l + 1];
        p.reg[l] = (const float*)d_in[3 * l + 2];
    }

    int nsm = 0;
    cudaDeviceGetAttribute(&nsm, cudaDevAttrMultiProcessorCount, 0);
    if (nsm <= 0) nsm = 148;
    int maxb = 0;
    cudaOccupancyMaxActiveBlocksPerMultiprocessor(&maxb, k_uber, 1024, 0);
    if (maxb < 1) maxb = 1;
    int nblk = nsm * maxb;   // guaranteed co-resident -> grid barrier is safe

    k_uber<<<nblk, 1024>>>(p, (float*)d_out, nblk);
}

// round 5
// speedup vs baseline: 2.3797x; 2.3062x over previous
#include <cuda_runtime.h>
#include <stdint.h>

typedef unsigned long long u64;
typedef unsigned int u32;

#define NLEV 5
#define CLSN 16
#define TOPK 1000
#define NTOT 785664
#define HBITS 13
#define HB (1 << HBITS)        /* 8192 bins: ord >> 19 */
#define WCAP 4096
#define CHUNK 1536
#define NCHUNK 512             /* 512*1536 = 786432 >= NTOT */
#define MAXD 4.135166556742356f

__device__ __constant__ int d_off[6] = {0, 589824, 737280, 774144, 783360, 785664};
__device__ __constant__ int d_len[5] = {589824, 147456, 36864, 9216, 2304};

struct Ptrs {
    const float* anc[NLEV];
    const float* cls[NLEV];
    const float* reg[NLEV];
};

// ---------------- scratch (static device globals; no allocation) ----------------
__device__ int g_hist[NLEV * HB];   // zeroed by memset node
__device__ int g_nwin[NLEV];        // zeroed by memset node
__device__ u32 g_ord[NTOT];
__device__ u64 g_win[NLEV][WCAP];
__device__ int g_thr[NLEV];

__device__ __forceinline__ int level_of(int a) {
    int l = 0;
#pragma unroll
    for (int j = 1; j < NLEV; j++) l += (a >= d_off[j]);
    return l;
}

// ---- K1: ruler (max of 16 logits) + PRIVATE shared 13-bit histogram ----
// Level-pure chunks of 1536 anchors; flush nonzero bins once per block.
__global__ void __launch_bounds__(512)
k_ruler(Ptrs p) {
    __shared__ u32 h[HB];                     // 32 KB
    const int t = threadIdx.x;
    for (int b = t; b < HB; b += 512) h[b] = 0;
    __syncthreads();

    const int cstart = blockIdx.x * CHUNK;
    const int l = level_of(cstart);
    const int base = d_off[l];
    const int iend = (cstart + CHUNK < NTOT) ? cstart + CHUNK : NTOT;
    const float4* cls4 = (const float4*)p.cls[l];

#pragma unroll
    for (int q = 0; q < 3; q++) {
        int a = cstart + q * 512 + t;
        if (a < iend) {
            int i = a - base;
            float4 va = cls4[i * 4 + 0], vb = cls4[i * 4 + 1];
            float4 vc = cls4[i * 4 + 2], vd = cls4[i * 4 + 3];
            float m = fmaxf(fmaxf(fmaxf(va.x, va.y), fmaxf(va.z, va.w)),
                            fmaxf(fmaxf(vb.x, vb.y), fmaxf(vb.z, vb.w)));
            m = fmaxf(m, fmaxf(fmaxf(vc.x, vc.y), fmaxf(vc.z, vc.w)));
            m = fmaxf(m, fmaxf(fmaxf(vd.x, vd.y), fmaxf(vd.z, vd.w)));
            u32 u = __float_as_uint(m);
            u32 ord = (u & 0x80000000u) ? ~u : (u | 0x80000000u);  // monotonic
            g_ord[a] = ord;
            atomicAdd(&h[ord >> (32 - HBITS)], 1u);
        }
    }
    __syncthreads();

    int* gh = &g_hist[l * HB];
    for (int b = t; b < HB; b += 512) {
        u32 c = h[b];
        if (c) atomicAdd(&gh[b], (int)c);     // <=384 adds per address (#blocks/level)
    }
}

// ---- K2: per-level threshold bin: largest B with suffix_count(B) >= TOPK ----
__global__ void k_resolve() {
    const int l = blockIdx.x;
    const int t = threadIdx.x;                // 256 threads
    const int CH = HB / 256;                  // 32 bins/thread
    __shared__ int csum[256];
    __shared__ int s_cidx, s_sufnext;
    const int* h = &g_hist[l * HB];

    int base = t * CH, s = 0;
#pragma unroll 4
    for (int j = 0; j < CH; j++) s += h[base + j];
    csum[t] = s;
    __syncthreads();
    for (int off = 1; off < 256; off <<= 1) { // reversed scan -> suffix sums
        int v = csum[t];
        int add = (t + off < 256) ? csum[t + off] : 0;
        __syncthreads();
        csum[t] = v + add;
        __syncthreads();
    }
    if (csum[t] >= TOPK && (t == 255 || csum[t + 1] < TOPK)) {
        s_cidx = t;
        s_sufnext = (t == 255) ? 0 : csum[t + 1];
    }
    __syncthreads();
    if (t == 0) {
        int cbase = s_cidx * CH;
        int suf = s_sufnext, b = cbase + CH - 1;
        for (int j = CH - 1; j >= 0; j--) {
            suf += h[cbase + j];
            b = cbase + j;
            if (suf >= TOPK) break;
        }
        g_thr[l] = b;
    }
}

// ---- K3: collect keys with top13 >= threshold (ballot-aggregated) ----
__global__ void __launch_bounds__(512)
k_select() {
    const int t = threadIdx.x;
    const int cstart = blockIdx.x * CHUNK;
    const int l = level_of(cstart);
    const int base = d_off[l];
    const int iend = (cstart + CHUNK < NTOT) ? cstart + CHUNK : NTOT;
    const u32 thr = (u32)g_thr[l];
    const int lane = t & 31;

#pragma unroll
    for (int q = 0; q < 3; q++) {
        int a = cstart + q * 512 + t;
        bool win = false;
        u32 ord = 0;
        if (a < iend) {
            ord = g_ord[a];
            win = (ord >> (32 - HBITS)) >= thr;
        }
        unsigned act = __activemask();
        unsigned mask = __ballot_sync(act, win);
        if (win) {
            int leader = __ffs(mask) - 1;
            int rk = __popc(mask & ((1u << lane) - 1));
            int wbase = 0;
            if (lane == leader) wbase = atomicAdd(&g_nwin[l], __popc(mask));
            wbase = __shfl_sync(mask, wbase, leader);
            int w = wbase + rk;
            if (w < WCAP) g_win[l][w] = ((u64)ord << 32) | (u32)(a - base);
        }
    }
}

// ---- K4: bitonic sort (value desc, idx asc) + decode + emit ----
__global__ void __launch_bounds__(1024)
k_rank_final(Ptrs p, float* __restrict__ out) {
    __shared__ u64 s[WCAP];       // 32 KB (reused as bbox after sort)
    __shared__ u32 sel[TOPK];     // 4 KB
    const int l = blockIdx.x;
    const int t = threadIdx.x;    // 1024
    int n = g_nwin[l];
    if (n > WCAP) n = WCAP;

    for (int i = t; i < WCAP; i += 1024)
        s[i] = (i < n) ? (g_win[l][i] ^ 0xFFFFFFFF00000000ULL)
                       : 0xFFFFFFFFFFFFFFFFULL;      // ascending (~ord, idx)
    __syncthreads();
    for (int k2 = 2; k2 <= WCAP; k2 <<= 1) {
        for (int j = k2 >> 1; j > 0; j >>= 1) {
            for (int i = t; i < WCAP; i += 1024) {
                int pr = i ^ j;
                if (pr > i) {
                    bool up = ((i & k2) == 0);
                    u64 x = s[i], y = s[pr];
                    if ((x > y) == up) { s[i] = y; s[pr] = x; }
                }
            }
            __syncthreads();
        }
    }
    if (t < TOPK) {
        u32 idx = (u32)(s[t] & 0xFFFFFFFFu);
        if (idx >= (u32)d_len[l]) idx = 0;   // safety (unwritten slots)
        sel[t] = idx;
    }
    __syncthreads();

    float4* bbox = (float4*)s;    // reuse sort storage (16 KB of 32 KB)
    if (t < TOPK) {
        u32 idx = sel[t];
        float4 a4 = ((const float4*)p.anc[l])[idx];
        float4 r4 = ((const float4*)p.reg[l])[idx * 2];
        float w = a4.z - a4.x, h = a4.w - a4.y;
        float cx = a4.x + 0.5f * w, cy = a4.y + 0.5f * h;
        float pcx = cx + r4.x * w, pcy = cy + r4.y * h;
        float pw = w * expf(fminf(r4.z, MAXD));
        float ph = h * expf(fminf(r4.w, MAXD));
        bbox[t] = make_float4(pcx - 0.5f * pw, pcy - 0.5f * ph,
                              pcx + 0.5f * pw, pcy + 0.5f * ph);
    }
    __syncthreads();

    const float* cls = p.cls[l];
    float* obase = out + (size_t)l * TOPK * CLSN * 6;
    for (int r0 = t; r0 < TOPK * CLSN; r0 += 1024) {
        int k = r0 >> 4, c = r0 & 15;
        u32 idx = sel[k];
        float score = cls[(size_t)idx * 16 + c];
        float sg = 1.0f / (1.0f + expf(-score));
        float4 b4 = bbox[k];
        float2* o = (float2*)(obase + (size_t)r0 * 6);
        o[0] = make_float2(b4.x, b4.y);
        o[1] = make_float2(b4.z, b4.w);
        o[2] = make_float2(sg, (float)(c + 1));
    }
}

extern "C" void kernel_launch(void* const* d_in, const int* in_sizes, int n_in,
                              void* d_out, int out_size) {
    (void)in_sizes; (void)n_in; (void)out_size;
    Ptrs p;
    for (int l = 0; l < NLEV; l++) {
        p.anc[l] = (const float*)d_in[3 * l + 0];
        p.cls[l] = (const float*)d_in[3 * l + 1];
        p.reg[l] = (const float*)d_in[3 * l + 2];
    }

    void* hist_ptr = nullptr;
    void* nwin_ptr = nullptr;
    cudaGetSymbolAddress(&hist_ptr, g_hist);
    cudaGetSymbolAddress(&nwin_ptr, g_nwin);
    cudaMemsetAsync(hist_ptr, 0, (size_t)NLEV * HB * sizeof(int), 0);
    cudaMemsetAsync(nwin_ptr, 0, (size_t)NLEV * sizeof(int), 0);

    k_ruler<<<NCHUNK, 512>>>(p);
    k_resolve<<<NLEV, 256>>>();
    k_select<<<NCHUNK, 512>>>();
    k_rank_final<<<NLEV, 1024>>>(p, (float*)d_out);
}

// round 6
// speedup vs baseline: 2.9169x; 1.2258x over previous
#include <cuda_runtime.h>
#include <stdint.h>

typedef unsigned long long u64;
typedef unsigned int u32;

#define NLEV 5
#define CLSN 16
#define TOPK 1000
#define NTOT 785664
#define HBITS 13
#define HB (1 << HBITS)        /* 8192 bins: ord >> 19 */
#define WCAP 4096
#define CHUNK 1536
#define NCHUNK 512             /* 512*1536 = 786432 >= NTOT */
#define MAXD 4.135166556742356f

__device__ __constant__ int d_off[6] = {0, 589824, 737280, 774144, 783360, 785664};
__device__ __constant__ int d_len[5] = {589824, 147456, 36864, 9216, 2304};

struct Ptrs {
    const float* anc[NLEV];
    const float* cls[NLEV];
    const float* reg[NLEV];
};

// ---------------- scratch (static device globals; no allocation) ----------------
__device__ int g_hist[NLEV * HB];   // zeroed by memset node
__device__ int g_nwin[NLEV];        // zeroed by memset node
__device__ u32 g_ord[NTOT];
__device__ u64 g_win[NLEV][WCAP];
__device__ int g_thr[NLEV];

__device__ __forceinline__ int level_of(int a) {
    int l = 0;
#pragma unroll
    for (int j = 1; j < NLEV; j++) l += (a >= d_off[j]);
    return l;
}

// ---- K1: ruler (max of 16 logits) + PRIVATE shared 13-bit histogram ----
__global__ void __launch_bounds__(512)
k_ruler(Ptrs p) {
    __shared__ u32 h[HB];                     // 32 KB
    const int t = threadIdx.x;
    for (int b = t; b < HB; b += 512) h[b] = 0;
    __syncthreads();

    const int cstart = blockIdx.x * CHUNK;
    const int l = level_of(cstart);
    const int base = d_off[l];
    const int iend = (cstart + CHUNK < NTOT) ? cstart + CHUNK : NTOT;
    const float4* cls4 = (const float4*)p.cls[l];

#pragma unroll
    for (int q = 0; q < 3; q++) {
        int a = cstart + q * 512 + t;
        if (a < iend) {
            int i = a - base;
            float4 va = cls4[i * 4 + 0], vb = cls4[i * 4 + 1];
            float4 vc = cls4[i * 4 + 2], vd = cls4[i * 4 + 3];
            float m = fmaxf(fmaxf(fmaxf(va.x, va.y), fmaxf(va.z, va.w)),
                            fmaxf(fmaxf(vb.x, vb.y), fmaxf(vb.z, vb.w)));
            m = fmaxf(m, fmaxf(fmaxf(vc.x, vc.y), fmaxf(vc.z, vc.w)));
            m = fmaxf(m, fmaxf(fmaxf(vd.x, vd.y), fmaxf(vd.z, vd.w)));
            u32 u = __float_as_uint(m);
            u32 ord = (u & 0x80000000u) ? ~u : (u | 0x80000000u);  // monotonic
            g_ord[a] = ord;
            atomicAdd(&h[ord >> (32 - HBITS)], 1u);
        }
    }
    __syncthreads();

    int* gh = &g_hist[l * HB];
    for (int b = t; b < HB; b += 512) {
        u32 c = h[b];
        if (c) atomicAdd(&gh[b], (int)c);     // <=384 adds per address
    }
}

// ---- K2: per-level threshold bin: largest B with suffix_count(B) >= TOPK ----
__global__ void k_resolve() {
    const int l = blockIdx.x;
    const int t = threadIdx.x;                // 256 threads
    const int CH = HB / 256;                  // 32 bins/thread
    __shared__ int csum[256];
    __shared__ int s_cidx, s_sufnext;
    const int* h = &g_hist[l * HB];

    int base = t * CH, s = 0;
#pragma unroll 4
    for (int j = 0; j < CH; j++) s += h[base + j];
    csum[t] = s;
    __syncthreads();
    for (int off = 1; off < 256; off <<= 1) { // reversed scan -> suffix sums
        int v = csum[t];
        int add = (t + off < 256) ? csum[t + off] : 0;
        __syncthreads();
        csum[t] = v + add;
        __syncthreads();
    }
    if (csum[t] >= TOPK && (t == 255 || csum[t + 1] < TOPK)) {
        s_cidx = t;
        s_sufnext = (t == 255) ? 0 : csum[t + 1];
    }
    __syncthreads();
    if (t == 0) {
        int cbase = s_cidx * CH;
        int suf = s_sufnext, b = cbase + CH - 1;
        for (int j = CH - 1; j >= 0; j--) {
            suf += h[cbase + j];
            b = cbase + j;
            if (suf >= TOPK) break;
        }
        g_thr[l] = b;
    }
}

// ---- K3: collect keys with top13 >= threshold (ballot-aggregated) ----
__global__ void __launch_bounds__(512)
k_select() {
    const int t = threadIdx.x;
    const int cstart = blockIdx.x * CHUNK;
    const int l = level_of(cstart);
    const int base = d_off[l];
    const int iend = (cstart + CHUNK < NTOT) ? cstart + CHUNK : NTOT;
    const u32 thr = (u32)g_thr[l];
    const int lane = t & 31;

#pragma unroll
    for (int q = 0; q < 3; q++) {
        int a = cstart + q * 512 + t;
        bool win = false;
        u32 ord = 0;
        if (a < iend) {
            ord = g_ord[a];
            win = (ord >> (32 - HBITS)) >= thr;
        }
        unsigned act = __activemask();
        unsigned mask = __ballot_sync(act, win);
        if (win) {
            int leader = __ffs(mask) - 1;
            int rk = __popc(mask & ((1u << lane) - 1));
            int wbase = 0;
            if (lane == leader) wbase = atomicAdd(&g_nwin[l], __popc(mask));
            wbase = __shfl_sync(mask, wbase, leader);
            int w = wbase + rk;
            if (w < WCAP) g_win[l][w] = ((u64)ord << 32) | (u32)(a - base);
        }
    }
}

// ---- K4: bitonic sort sized to n (value desc, idx asc) + decode + emit ----
__global__ void __launch_bounds__(1024)
k_rank_final(Ptrs p, float* __restrict__ out) {
    __shared__ u64 s[WCAP];       // 32 KB (reused as bbox after sort)
    __shared__ u32 sel[TOPK];     // 4 KB
    const int l = blockIdx.x;
    const int t = threadIdx.x;    // 1024
    int n = g_nwin[l];
    if (n > WCAP) n = WCAP;

    // M = smallest power of two >= max(n, TOPK); typically 2048
    int M = 1024;
    while (M < n) M <<= 1;

    for (int i = t; i < M; i += 1024)
        s[i] = (i < n) ? (g_win[l][i] ^ 0xFFFFFFFF00000000ULL)
                       : 0xFFFFFFFFFFFFFFFFULL;      // ascending (~ord, idx)
    __syncthreads();
    for (int k2 = 2; k2 <= M; k2 <<= 1) {
        for (int j = k2 >> 1; j > 0; j >>= 1) {
            for (int i = t; i < M; i += 1024) {
                int pr = i ^ j;
                if (pr > i) {
                    bool up = ((i & k2) == 0);
                    u64 x = s[i], y = s[pr];
                    if ((x > y) == up) { s[i] = y; s[pr] = x; }
                }
            }
            __syncthreads();
        }
    }
    if (t < TOPK) {
        u32 idx = (u32)(s[t] & 0xFFFFFFFFu);
        if (idx >= (u32)d_len[l]) idx = 0;   // safety (unwritten slots)
        sel[t] = idx;
    }
    __syncthreads();

    float4* bbox = (float4*)s;    // reuse sort storage (16 KB of 32 KB)
    if (t < TOPK) {
        u32 idx = sel[t];
        float4 a4 = ((const float4*)p.anc[l])[idx];
        float4 r4 = ((const float4*)p.reg[l])[idx * 2];
        float w = a4.z - a4.x, h = a4.w - a4.y;
        float cx = a4.x + 0.5f * w, cy = a4.y + 0.5f * h;
        float pcx = cx + r4.x * w, pcy = cy + r4.y * h;
        float pw = w * expf(fminf(r4.z, MAXD));
        float ph = h * expf(fminf(r4.w, MAXD));
        bbox[t] = make_float4(pcx - 0.5f * pw, pcy - 0.5f * ph,
                              pcx + 0.5f * pw, pcy + 0.5f * ph);
    }
    __syncthreads();

    const float* cls = p.cls[l];
    float* obase = out + (size_t)l * TOPK * CLSN * 6;
    for (int r0 = t; r0 < TOPK * CLSN; r0 += 1024) {
        int k = r0 >> 4, c = r0 & 15;
        u32 idx = sel[k];
        float score = cls[(size_t)idx * 16 + c];
        float sg = 1.0f / (1.0f + expf(-score));
        float4 b4 = bbox[k];
        float2* o = (float2*)(obase + (size_t)r0 * 6);
        o[0] = make_float2(b4.x, b4.y);
        o[1] = make_float2(b4.z, b4.w);
        o[2] = make_float2(sg, (float)(c + 1));
    }
}

extern "C" void kernel_launch(void* const* d_in, const int* in_sizes, int n_in,
                              void* d_out, int out_size) {
    (void)in_sizes; (void)n_in; (void)out_size;
    Ptrs p;
    for (int l = 0; l < NLEV; l++) {
        p.anc[l] = (const float*)d_in[3 * l + 0];
        p.cls[l] = (const float*)d_in[3 * l + 1];
        p.reg[l] = (const float*)d_in[3 * l + 2];
    }

    void* hist_ptr = nullptr;
    void* nwin_ptr = nullptr;
    cudaGetSymbolAddress(&hist_ptr, g_hist);
    cudaGetSymbolAddress(&nwin_ptr, g_nwin);
    cudaMemsetAsync(hist_ptr, 0, (size_t)NLEV * HB * sizeof(int), 0);
    cudaMemsetAsync(nwin_ptr, 0, (size_t)NLEV * sizeof(int), 0);

    k_ruler<<<NCHUNK, 512>>>(p);
    k_resolve<<<NLEV, 256>>>();
    k_select<<<NCHUNK, 512>>>();
    k_rank_final<<<NLEV, 1024>>>(p, (float*)d_out);
}

// round 7
// speedup vs baseline: 3.1737x; 1.0880x over previous
#include <cuda_runtime.h>
#include <stdint.h>

typedef unsigned long long u64;
typedef unsigned int u32;

#define NLEV 5
#define CLSN 16
#define TOPK 1000
#define NTOT 785664
#define HBITS 13
#define HB (1 << HBITS)        /* 8192 bins: ord >> 19 */
#define WCAP 4096
#define CHUNK 1536
#define NCHUNK 512             /* 512*1536 = 786432 >= NTOT */
#define MAXD 4.135166556742356f

__device__ __constant__ int d_off[6] = {0, 589824, 737280, 774144, 783360, 785664};
__device__ __constant__ int d_len[5] = {589824, 147456, 36864, 9216, 2304};

struct Ptrs {
    const float* anc[NLEV];
    const float* cls[NLEV];
    const float* reg[NLEV];
};

// ---------------- scratch (static device globals; no allocation) ----------------
__device__ int g_hist[NLEV * HB];   // zeroed by memset node
__device__ int g_nwin[NLEV];        // zeroed by memset node
__device__ u32 g_ord[NTOT];
__device__ u64 g_win[NLEV][WCAP];
__device__ int g_thr[NLEV];

__device__ __forceinline__ int level_of(int a) {
    int l = 0;
#pragma unroll
    for (int j = 1; j < NLEV; j++) l += (a >= d_off[j]);
    return l;
}

__device__ __forceinline__ u64 u64min(u64 a, u64 b) { return a < b ? a : b; }
__device__ __forceinline__ u64 u64max(u64 a, u64 b) { return a > b ? a : b; }

// ---- K1: ruler (max of 16 logits) + PRIVATE shared 13-bit histogram ----
__global__ void __launch_bounds__(512)
k_ruler(Ptrs p) {
    __shared__ u32 h[HB];                     // 32 KB
    const int t = threadIdx.x;
    for (int b = t; b < HB; b += 512) h[b] = 0;
    __syncthreads();

    const int cstart = blockIdx.x * CHUNK;
    const int l = level_of(cstart);
    const int base = d_off[l];
    const int iend = (cstart + CHUNK < NTOT) ? cstart + CHUNK : NTOT;
    const float4* cls4 = (const float4*)p.cls[l];

#pragma unroll
    for (int q = 0; q < 3; q++) {
        int a = cstart + q * 512 + t;
        if (a < iend) {
            int i = a - base;
            float4 va = cls4[i * 4 + 0], vb = cls4[i * 4 + 1];
            float4 vc = cls4[i * 4 + 2], vd = cls4[i * 4 + 3];
            float m = fmaxf(fmaxf(fmaxf(va.x, va.y), fmaxf(va.z, va.w)),
                            fmaxf(fmaxf(vb.x, vb.y), fmaxf(vb.z, vb.w)));
            m = fmaxf(m, fmaxf(fmaxf(vc.x, vc.y), fmaxf(vc.z, vc.w)));
            m = fmaxf(m, fmaxf(fmaxf(vd.x, vd.y), fmaxf(vd.z, vd.w)));
            u32 u = __float_as_uint(m);
            u32 ord = (u & 0x80000000u) ? ~u : (u | 0x80000000u);  // monotonic
            g_ord[a] = ord;
            atomicAdd(&h[ord >> (32 - HBITS)], 1u);
        }
    }
    __syncthreads();

    int* gh = &g_hist[l * HB];
    for (int b = t; b < HB; b += 512) {
        u32 c = h[b];
        if (c) atomicAdd(&gh[b], (int)c);     // <=384 adds per address
    }
}

// ---- K2: per-level threshold bin: largest B with suffix_count(B) >= TOPK ----
__global__ void k_resolve() {
    const int l = blockIdx.x;
    const int t = threadIdx.x;                // 256 threads
    const int CH = HB / 256;                  // 32 bins/thread
    __shared__ int csum[256];
    __shared__ int s_cidx, s_sufnext;
    const int* h = &g_hist[l * HB];

    int base = t * CH, s = 0;
#pragma unroll 4
    for (int j = 0; j < CH; j++) s += h[base + j];
    csum[t] = s;
    __syncthreads();
    for (int off = 1; off < 256; off <<= 1) { // reversed scan -> suffix sums
        int v = csum[t];
        int add = (t + off < 256) ? csum[t + off] : 0;
        __syncthreads();
        csum[t] = v + add;
        __syncthreads();
    }
    if (csum[t] >= TOPK && (t == 255 || csum[t + 1] < TOPK)) {
        s_cidx = t;
        s_sufnext = (t == 255) ? 0 : csum[t + 1];
    }
    __syncthreads();
    if (t == 0) {
        int cbase = s_cidx * CH;
        int suf = s_sufnext, b = cbase + CH - 1;
        for (int j = CH - 1; j >= 0; j--) {
            suf += h[cbase + j];
            b = cbase + j;
            if (suf >= TOPK) break;
        }
        g_thr[l] = b;
    }
}

// ---- K3: collect keys with top13 >= threshold (ballot-aggregated) ----
__global__ void __launch_bounds__(512)
k_select() {
    const int t = threadIdx.x;
    const int cstart = blockIdx.x * CHUNK;
    const int l = level_of(cstart);
    const int base = d_off[l];
    const int iend = (cstart + CHUNK < NTOT) ? cstart + CHUNK : NTOT;
    const u32 thr = (u32)g_thr[l];
    const int lane = t & 31;

#pragma unroll
    for (int q = 0; q < 3; q++) {
        int a = cstart + q * 512 + t;
        bool win = false;
        u32 ord = 0;
        if (a < iend) {
            ord = g_ord[a];
            win = (ord >> (32 - HBITS)) >= thr;
        }
        unsigned act = __activemask();
        unsigned mask = __ballot_sync(act, win);
        if (win) {
            int leader = __ffs(mask) - 1;
            int rk = __popc(mask & ((1u << lane) - 1));
            int wbase = 0;
            if (lane == leader) wbase = atomicAdd(&g_nwin[l], __popc(mask));
            wbase = __shfl_sync(mask, wbase, leader);
            int w = wbase + rk;
            if (w < WCAP) g_win[l][w] = ((u64)ord << 32) | (u32)(a - base);
        }
    }
}

// ---- K4: register bitonic sort (value desc, idx asc) + decode + emit ----
__global__ void __launch_bounds__(1024)
k_rank_final(Ptrs p, float* __restrict__ out) {
    __shared__ u64 s[2048];       // 16 KB exchange buffer (reused as bbox)
    __shared__ u32 sel[TOPK];     // 4 KB
    const int l = blockIdx.x;
    const int t = threadIdx.x;    // 1024
    const int lane = t & 31;
    int n = g_nwin[l];
    if (n > WCAP) n = WCAP;

    if (n <= 2048) {
        // fast path: 2048-wide bitonic, 2 keys per thread, shfl for j<=16
        const int i0 = (t >> 5) * 64 + lane;   // warp-owned 64-element span
        const int i1 = i0 + 32;
        u64 v0 = (i0 < n) ? (g_win[l][i0] ^ 0xFFFFFFFF00000000ULL) : ~0ULL;
        u64 v1 = (i1 < n) ? (g_win[l][i1] ^ 0xFFFFFFFF00000000ULL) : ~0ULL;

        for (int k2 = 2; k2 <= 2048; k2 <<= 1) {
            // smem phases: j >= 64 (cross-warp)
            for (int j = k2 >> 1; j >= 64; j >>= 1) {
                s[i0] = v0;
                s[i1] = v1;
                __syncthreads();
                u64 p0 = s[i0 ^ j], p1 = s[i1 ^ j];
                bool up0 = ((i0 & k2) == 0);
                bool up1 = ((i1 & k2) == 0);
                v0 = (((i0 & j) == 0) == up0) ? u64min(v0, p0) : u64max(v0, p0);
                v1 = (((i1 & j) == 0) == up1) ? u64min(v1, p1) : u64max(v1, p1);
                __syncthreads();
            }
            // j == 32: exchange between the two registers of this thread
            if (k2 >= 64) {
                bool up = ((i0 & k2) == 0);    // i0,i1 share the k2 bit (k2>=64)
                u64 lo = u64min(v0, v1), hi = u64max(v0, v1);
                v0 = up ? lo : hi;
                v1 = up ? hi : lo;
            }
            // j <= 16: warp shuffles, no barriers
            int jstart = (k2 >> 1 < 16) ? (k2 >> 1) : 16;
            for (int j = jstart; j >= 1; j >>= 1) {
                bool up0 = ((i0 & k2) == 0);
                bool up1 = ((i1 & k2) == 0);
                u64 o0 = __shfl_xor_sync(0xFFFFFFFFu, v0, j);
                u64 o1 = __shfl_xor_sync(0xFFFFFFFFu, v1, j);
                bool lower = ((lane & j) == 0);
                v0 = (lower == up0) ? u64min(v0, o0) : u64max(v0, o0);
                v1 = (lower == up1) ? u64min(v1, o1) : u64max(v1, o1);
            }
        }
        if (i0 < TOPK) {
            u32 idx = (u32)(v0 & 0xFFFFFFFFu);
            if (idx >= (u32)d_len[l]) idx = 0;
            sel[i0] = idx;
        }
        if (i1 < TOPK) {
            u32 idx = (u32)(v1 & 0xFFFFFFFFu);
            if (idx >= (u32)d_len[l]) idx = 0;
            sel[i1] = idx;
        }
        __syncthreads();
    } else {
        // generic fallback (n in (2048, 4096]): rank-select via per-key count
        for (int i = t; i < TOPK; i += 1024) sel[i] = 0;
        __syncthreads();
        for (int i = t; i < n; i += 1024) {
            u64 me = g_win[l][i] ^ 0xFFFFFFFF00000000ULL;
            int rank = 0;
            for (int j = 0; j < n; j++)
                rank += ((g_win[l][j] ^ 0xFFFFFFFF00000000ULL) < me);
            if (rank < TOPK) {
                u32 idx = (u32)(me & 0xFFFFFFFFu);
                if (idx >= (u32)d_len[l]) idx = 0;
                sel[rank] = idx;
            }
        }
        __syncthreads();
    }

    // decode 1000 boxes into smem (reuse sort buffer)
    float4* bbox = (float4*)s;
    if (t < TOPK) {
        u32 idx = sel[t];
        float4 a4 = ((const float4*)p.anc[l])[idx];
        float4 r4 = ((const float4*)p.reg[l])[idx * 2];
        float w = a4.z - a4.x, h = a4.w - a4.y;
        float cx = a4.x + 0.5f * w, cy = a4.y + 0.5f * h;
        float pcx = cx + r4.x * w, pcy = cy + r4.y * h;
        float pw = w * expf(fminf(r4.z, MAXD));
        float ph = h * expf(fminf(r4.w, MAXD));
        bbox[t] = make_float4(pcx - 0.5f * pw, pcy - 0.5f * ph,
                              pcx + 0.5f * pw, pcy + 0.5f * ph);
    }
    __syncthreads();

    // emit 16000 rows for this level
    const float* cls = p.cls[l];
    float* obase = out + (size_t)l * TOPK * CLSN * 6;
    for (int r0 = t; r0 < TOPK * CLSN; r0 += 1024) {
        int k = r0 >> 4, c = r0 & 15;
        u32 idx = sel[k];
        float score = cls[(size_t)idx * 16 + c];
        float sg = 1.0f / (1.0f + expf(-score));
        float4 b4 = bbox[k];
        float2* o = (float2*)(obase + (size_t)r0 * 6);
        o[0] = make_float2(b4.x, b4.y);
        o[1] = make_float2(b4.z, b4.w);
        o[2] = make_float2(sg, (float)(c + 1));
    }
}

extern "C" void kernel_launch(void* const* d_in, const int* in_sizes, int n_in,
                              void* d_out, int out_size) {
    (void)in_sizes; (void)n_in; (void)out_size;
    Ptrs p;
    for (int l = 0; l < NLEV; l++) {
        p.anc[l] = (const float*)d_in[3 * l + 0];
        p.cls[l] = (const float*)d_in[3 * l + 1];
        p.reg[l] = (const float*)d_in[3 * l + 2];
    }

    void* hist_ptr = nullptr;
    void* nwin_ptr = nullptr;
    cudaGetSymbolAddress(&hist_ptr, g_hist);
    cudaGetSymbolAddress(&nwin_ptr, g_nwin);
    cudaMemsetAsync(hist_ptr, 0, (size_t)NLEV * HB * sizeof(int), 0);
    cudaMemsetAsync(nwin_ptr, 0, (size_t)NLEV * sizeof(int), 0);

    k_ruler<<<NCHUNK, 512>>>(p);
    k_resolve<<<NLEV, 256>>>();
    k_select<<<NCHUNK, 512>>>();
    k_rank_final<<<NLEV, 1024>>>(p, (float*)d_out);
}

// round 8
// speedup vs baseline: 4.1886x; 1.3198x over previous
#include <cuda_runtime.h>
#include <stdint.h>

typedef unsigned long long u64;
typedef unsigned int u32;

#define NLEV 5
#define CLSN 16
#define TOPK 1000
#define NTOT 785664
#define KTOT (NLEV * TOPK)
#define HBITS 13
#define HB (1 << HBITS)        /* 8192 bins: ord >> 19 */
#define WCAP 4096
#define CHUNK 1536
#define NCHUNK 512             /* 512*1536 = 786432 >= NTOT */
#define MAXD 4.135166556742356f

__device__ __constant__ int d_off[6] = {0, 589824, 737280, 774144, 783360, 785664};
__device__ __constant__ int d_len[5] = {589824, 147456, 36864, 9216, 2304};

struct Ptrs {
    const float* anc[NLEV];
    const float* cls[NLEV];
    const float* reg[NLEV];
};

// ---------------- scratch (static device globals; no allocation) ----------------
__device__ int g_hist[NLEV * HB];   // zeroed by memset node
__device__ int g_nwin[NLEV];        // zeroed by memset node
__device__ u32 g_ord[NTOT];
__device__ u64 g_win[NLEV][WCAP];
__device__ int g_thr[NLEV];
__device__ u32 g_sel[KTOT];

__device__ __forceinline__ int level_of(int a) {
    int l = 0;
#pragma unroll
    for (int j = 1; j < NLEV; j++) l += (a >= d_off[j]);
    return l;
}

__device__ __forceinline__ u64 u64min(u64 a, u64 b) { return a < b ? a : b; }
__device__ __forceinline__ u64 u64max(u64 a, u64 b) { return a > b ? a : b; }

// ---- K1: ruler (max of 16 logits) + PRIVATE shared 13-bit histogram ----
__global__ void __launch_bounds__(512)
k_ruler(Ptrs p) {
    __shared__ u32 h[HB];                     // 32 KB
    const int t = threadIdx.x;
    for (int b = t; b < HB; b += 512) h[b] = 0;
    __syncthreads();

    const int cstart = blockIdx.x * CHUNK;
    const int l = level_of(cstart);
    const int base = d_off[l];
    const int iend = (cstart + CHUNK < NTOT) ? cstart + CHUNK : NTOT;
    const float4* cls4 = (const float4*)p.cls[l];

#pragma unroll
    for (int q = 0; q < 3; q++) {
        int a = cstart + q * 512 + t;
        if (a < iend) {
            int i = a - base;
            float4 va = cls4[i * 4 + 0], vb = cls4[i * 4 + 1];
            float4 vc = cls4[i * 4 + 2], vd = cls4[i * 4 + 3];
            float m = fmaxf(fmaxf(fmaxf(va.x, va.y), fmaxf(va.z, va.w)),
                            fmaxf(fmaxf(vb.x, vb.y), fmaxf(vb.z, vb.w)));
            m = fmaxf(m, fmaxf(fmaxf(vc.x, vc.y), fmaxf(vc.z, vc.w)));
            m = fmaxf(m, fmaxf(fmaxf(vd.x, vd.y), fmaxf(vd.z, vd.w)));
            u32 u = __float_as_uint(m);
            u32 ord = (u & 0x80000000u) ? ~u : (u | 0x80000000u);  // monotonic
            g_ord[a] = ord;
            atomicAdd(&h[ord >> (32 - HBITS)], 1u);
        }
    }
    __syncthreads();

    int* gh = &g_hist[l * HB];
    for (int b = t; b < HB; b += 512) {
        u32 c = h[b];
        if (c) atomicAdd(&gh[b], (int)c);     // <=384 adds per address
    }
}

// ---- K2: per-level threshold bin: largest B with suffix_count(B) >= TOPK ----
__global__ void k_resolve() {
    const int l = blockIdx.x;
    const int t = threadIdx.x;                // 256 threads
    const int CH = HB / 256;                  // 32 bins/thread
    __shared__ int csum[256];
    __shared__ int s_cidx, s_sufnext;
    const int* h = &g_hist[l * HB];

    int base = t * CH, s = 0;
#pragma unroll 4
    for (int j = 0; j < CH; j++) s += h[base + j];
    csum[t] = s;
    __syncthreads();
    for (int off = 1; off < 256; off <<= 1) { // reversed scan -> suffix sums
        int v = csum[t];
        int add = (t + off < 256) ? csum[t + off] : 0;
        __syncthreads();
        csum[t] = v + add;
        __syncthreads();
    }
    if (csum[t] >= TOPK && (t == 255 || csum[t + 1] < TOPK)) {
        s_cidx = t;
        s_sufnext = (t == 255) ? 0 : csum[t + 1];
    }
    __syncthreads();
    if (t == 0) {
        int cbase = s_cidx * CH;
        int suf = s_sufnext, b = cbase + CH - 1;
        for (int j = CH - 1; j >= 0; j--) {
            suf += h[cbase + j];
            b = cbase + j;
            if (suf >= TOPK) break;
        }
        g_thr[l] = b;
    }
}

// ---- K3: collect keys with top13 >= threshold (ballot-aggregated) ----
__global__ void __launch_bounds__(512)
k_select() {
    const int t = threadIdx.x;
    const int cstart = blockIdx.x * CHUNK;
    const int l = level_of(cstart);
    const int base = d_off[l];
    const int iend = (cstart + CHUNK < NTOT) ? cstart + CHUNK : NTOT;
    const u32 thr = (u32)g_thr[l];
    const int lane = t & 31;

#pragma unroll
    for (int q = 0; q < 3; q++) {
        int a = cstart + q * 512 + t;
        bool win = false;
        u32 ord = 0;
        if (a < iend) {
            ord = g_ord[a];
            win = (ord >> (32 - HBITS)) >= thr;
        }
        unsigned act = __activemask();
        unsigned mask = __ballot_sync(act, win);
        if (win) {
            int leader = __ffs(mask) - 1;
            int rk = __popc(mask & ((1u << lane) - 1));
            int wbase = 0;
            if (lane == leader) wbase = atomicAdd(&g_nwin[l], __popc(mask));
            wbase = __shfl_sync(mask, wbase, leader);
            int w = wbase + rk;
            if (w < WCAP) g_win[l][w] = ((u64)ord << 32) | (u32)(a - base);
        }
    }
}

// ---- K4: register bitonic sort (value desc, idx asc) -> g_sel ----
__global__ void __launch_bounds__(1024)
k_sort() {
    __shared__ u64 s[2048];       // 16 KB exchange buffer
    const int l = blockIdx.x;
    const int t = threadIdx.x;    // 1024
    const int lane = t & 31;
    int n = g_nwin[l];
    if (n > WCAP) n = WCAP;

    if (n <= 2048) {
        // fast path: 2048-wide bitonic, 2 keys per thread, shfl for j<=16
        const int i0 = (t >> 5) * 64 + lane;   // warp-owned 64-element span
        const int i1 = i0 + 32;
        u64 v0 = (i0 < n) ? (g_win[l][i0] ^ 0xFFFFFFFF00000000ULL) : ~0ULL;
        u64 v1 = (i1 < n) ? (g_win[l][i1] ^ 0xFFFFFFFF00000000ULL) : ~0ULL;

        for (int k2 = 2; k2 <= 2048; k2 <<= 1) {
            for (int j = k2 >> 1; j >= 64; j >>= 1) {   // cross-warp via smem
                s[i0] = v0;
                s[i1] = v1;
                __syncthreads();
                u64 p0 = s[i0 ^ j], p1 = s[i1 ^ j];
                bool up0 = ((i0 & k2) == 0);
                bool up1 = ((i1 & k2) == 0);
                v0 = (((i0 & j) == 0) == up0) ? u64min(v0, p0) : u64max(v0, p0);
                v1 = (((i1 & j) == 0) == up1) ? u64min(v1, p1) : u64max(v1, p1);
                __syncthreads();
            }
            if (k2 >= 64) {                    // j == 32: in-thread swap
                bool up = ((i0 & k2) == 0);
                u64 lo = u64min(v0, v1), hi = u64max(v0, v1);
                v0 = up ? lo : hi;
                v1 = up ? hi : lo;
            }
            int jstart = (k2 >> 1 < 16) ? (k2 >> 1) : 16;
            for (int j = jstart; j >= 1; j >>= 1) {     // warp shuffles
                bool up0 = ((i0 & k2) == 0);
                bool up1 = ((i1 & k2) == 0);
                u64 o0 = __shfl_xor_sync(0xFFFFFFFFu, v0, j);
                u64 o1 = __shfl_xor_sync(0xFFFFFFFFu, v1, j);
                bool lower = ((lane & j) == 0);
                v0 = (lower == up0) ? u64min(v0, o0) : u64max(v0, o0);
                v1 = (lower == up1) ? u64min(v1, o1) : u64max(v1, o1);
            }
        }
        if (i0 < TOPK) {
            u32 idx = (u32)(v0 & 0xFFFFFFFFu);
            if (idx >= (u32)d_len[l]) idx = 0;
            g_sel[l * TOPK + i0] = idx;
        }
        if (i1 < TOPK) {
            u32 idx = (u32)(v1 & 0xFFFFFFFFu);
            if (idx >= (u32)d_len[l]) idx = 0;
            g_sel[l * TOPK + i1] = idx;
        }
    } else {
        // generic fallback (n in (2048, 4096]): exact rank-select
        for (int i = t; i < n; i += 1024) {
            u64 me = g_win[l][i] ^ 0xFFFFFFFF00000000ULL;
            int rank = 0;
            for (int j = 0; j < n; j++)
                rank += ((g_win[l][j] ^ 0xFFFFFFFF00000000ULL) < me);
            if (rank < TOPK) {
                u32 idx = (u32)(me & 0xFFFFFFFFu);
                if (idx >= (u32)d_len[l]) idx = 0;
                g_sel[l * TOPK + rank] = idx;
            }
        }
    }
}

// ---- K5: decode + emit, massively parallel (grid 125 x 5, 128 thr) ----
// Each block: 8 boxes -> 128 output rows.
__global__ void __launch_bounds__(128)
k_emit(Ptrs p, float* __restrict__ out) {
    __shared__ float4 bbox[8];
    __shared__ u32 sidx[8];
    const int l = blockIdx.y;
    const int kloc = blockIdx.x * 8;
    const int t = threadIdx.x;

    if (t < 8) {
        u32 idx = g_sel[l * TOPK + kloc + t];
        if (idx >= (u32)d_len[l]) idx = 0;     // safety
        sidx[t] = idx;
        float4 a4 = ((const float4*)p.anc[l])[idx];
        float4 r4 = ((const float4*)p.reg[l])[idx * 2];
        float w = a4.z - a4.x, h = a4.w - a4.y;
        float cx = a4.x + 0.5f * w, cy = a4.y + 0.5f * h;
        float pcx = cx + r4.x * w, pcy = cy + r4.y * h;
        float pw = w * expf(fminf(r4.z, MAXD));
        float ph = h * expf(fminf(r4.w, MAXD));
        bbox[t] = make_float4(pcx - 0.5f * pw, pcy - 0.5f * ph,
                              pcx + 0.5f * pw, pcy + 0.5f * ph);
    }
    __syncthreads();

    const int k = t >> 4;          // 0..7
    const int c = t & 15;
    u32 idx = sidx[k];
    float score = p.cls[l][(size_t)idx * 16 + c];
    float sg = 1.0f / (1.0f + expf(-score));
    float4 b4 = bbox[k];
    float* o = out + ((size_t)(l * TOPK + kloc + k) * CLSN + c) * 6;
    float2* o2 = (float2*)o;
    o2[0] = make_float2(b4.x, b4.y);
    o2[1] = make_float2(b4.z, b4.w);
    o2[2] = make_float2(sg, (float)(c + 1));
}

extern "C" void kernel_launch(void* const* d_in, const int* in_sizes, int n_in,
                              void* d_out, int out_size) {
    (void)in_sizes; (void)n_in; (void)out_size;
    Ptrs p;
    for (int l = 0; l < NLEV; l++) {
        p.anc[l] = (const float*)d_in[3 * l + 0];
        p.cls[l] = (const float*)d_in[3 * l + 1];
        p.reg[l] = (const float*)d_in[3 * l + 2];
    }

    void* hist_ptr = nullptr;
    void* nwin_ptr = nullptr;
    cudaGetSymbolAddress(&hist_ptr, g_hist);
    cudaGetSymbolAddress(&nwin_ptr, g_nwin);
    cudaMemsetAsync(hist_ptr, 0, (size_t)NLEV * HB * sizeof(int), 0);
    cudaMemsetAsync(nwin_ptr, 0, (size_t)NLEV * sizeof(int), 0);

    k_ruler<<<NCHUNK, 512>>>(p);
    k_resolve<<<NLEV, 256>>>();
    k_select<<<NCHUNK, 512>>>();
    k_sort<<<NLEV, 1024>>>();
    dim3 ge(TOPK / 8, NLEV);
    k_emit<<<ge, 128>>>(p, (float*)d_out);
}

// round 9
// speedup vs baseline: 4.3630x; 1.0416x over previous
#include <cuda_runtime.h>
#include <stdint.h>

typedef unsigned long long u64;
typedef unsigned int u32;

#define NLEV 5
#define CLSN 16
#define TOPK 1000
#define NTOT 785664
#define KTOT (NLEV * TOPK)
#define HBITS 13
#define HB (1 << HBITS)        /* 8192 bins: ord >> 19 */
#define WCAP 4096
#define CHUNK 1536
#define NCHUNK 512             /* 512*1536 = 786432 >= NTOT */
#define RBLK 256               /* threads per rank block */
#define MAXD 4.135166556742356f

__device__ __constant__ int d_off[6] = {0, 589824, 737280, 774144, 783360, 785664};
__device__ __constant__ int d_len[5] = {589824, 147456, 36864, 9216, 2304};

struct Ptrs {
    const float* anc[NLEV];
    const float* cls[NLEV];
    const float* reg[NLEV];
};

// ---------------- scratch (static device globals; no allocation) ----------------
__device__ int g_hist[NLEV * HB];   // zeroed by memset node
__device__ int g_nwin[NLEV];        // zeroed by memset node
__device__ u32 g_ord[NTOT];
__device__ u64 g_win[NLEV][WCAP];
__device__ int g_thr[NLEV];
__device__ u32 g_sel[KTOT];

__device__ __forceinline__ int level_of(int a) {
    int l = 0;
#pragma unroll
    for (int j = 1; j < NLEV; j++) l += (a >= d_off[j]);
    return l;
}

// ---- K1: ruler (max of 16 logits) + PRIVATE shared 13-bit histogram ----
__global__ void __launch_bounds__(512)
k_ruler(Ptrs p) {
    __shared__ u32 h[HB];                     // 32 KB
    const int t = threadIdx.x;
    for (int b = t; b < HB; b += 512) h[b] = 0;
    __syncthreads();

    const int cstart = blockIdx.x * CHUNK;
    const int l = level_of(cstart);
    const int base = d_off[l];
    const int iend = (cstart + CHUNK < NTOT) ? cstart + CHUNK : NTOT;
    const float4* cls4 = (const float4*)p.cls[l];

#pragma unroll
    for (int q = 0; q < 3; q++) {
        int a = cstart + q * 512 + t;
        if (a < iend) {
            int i = a - base;
            float4 va = cls4[i * 4 + 0], vb = cls4[i * 4 + 1];
            float4 vc = cls4[i * 4 + 2], vd = cls4[i * 4 + 3];
            float m = fmaxf(fmaxf(fmaxf(va.x, va.y), fmaxf(va.z, va.w)),
                            fmaxf(fmaxf(vb.x, vb.y), fmaxf(vb.z, vb.w)));
            m = fmaxf(m, fmaxf(fmaxf(vc.x, vc.y), fmaxf(vc.z, vc.w)));
            m = fmaxf(m, fmaxf(fmaxf(vd.x, vd.y), fmaxf(vd.z, vd.w)));
            u32 u = __float_as_uint(m);
            u32 ord = (u & 0x80000000u) ? ~u : (u | 0x80000000u);  // monotonic
            g_ord[a] = ord;
            atomicAdd(&h[ord >> (32 - HBITS)], 1u);
        }
    }
    __syncthreads();

    int* gh = &g_hist[l * HB];
    for (int b = t; b < HB; b += 512) {
        u32 c = h[b];
        if (c) atomicAdd(&gh[b], (int)c);     // <=384 adds per address
    }
}

// ---- K2: per-level threshold bin: largest B with suffix_count(B) >= TOPK ----
__global__ void k_resolve() {
    const int l = blockIdx.x;
    const int t = threadIdx.x;                // 256 threads
    const int CH = HB / 256;                  // 32 bins/thread
    __shared__ int csum[256];
    __shared__ int s_cidx, s_sufnext;
    const int* h = &g_hist[l * HB];

    int base = t * CH, s = 0;
#pragma unroll 4
    for (int j = 0; j < CH; j++) s += h[base + j];
    csum[t] = s;
    __syncthreads();
    for (int off = 1; off < 256; off <<= 1) { // reversed scan -> suffix sums
        int v = csum[t];
        int add = (t + off < 256) ? csum[t + off] : 0;
        __syncthreads();
        csum[t] = v + add;
        __syncthreads();
    }
    if (csum[t] >= TOPK && (t == 255 || csum[t + 1] < TOPK)) {
        s_cidx = t;
        s_sufnext = (t == 255) ? 0 : csum[t + 1];
    }
    __syncthreads();
    if (t == 0) {
        int cbase = s_cidx * CH;
        int suf = s_sufnext, b = cbase + CH - 1;
        for (int j = CH - 1; j >= 0; j--) {
            suf += h[cbase + j];
            b = cbase + j;
            if (suf >= TOPK) break;
        }
        g_thr[l] = b;
    }
}

// ---- K3: collect keys with top13 >= threshold (ballot-aggregated) ----
__global__ void __launch_bounds__(512)
k_select() {
    const int t = threadIdx.x;
    const int cstart = blockIdx.x * CHUNK;
    const int l = level_of(cstart);
    const int base = d_off[l];
    const int iend = (cstart + CHUNK < NTOT) ? cstart + CHUNK : NTOT;
    const u32 thr = (u32)g_thr[l];
    const int lane = t & 31;

#pragma unroll
    for (int q = 0; q < 3; q++) {
        int a = cstart + q * 512 + t;
        bool win = false;
        u32 ord = 0;
        if (a < iend) {
            ord = g_ord[a];
            win = (ord >> (32 - HBITS)) >= thr;
        }
        unsigned act = __activemask();
        unsigned mask = __ballot_sync(act, win);
        if (win) {
            int leader = __ffs(mask) - 1;
            int rk = __popc(mask & ((1u << lane) - 1));
            int wbase = 0;
            if (lane == leader) wbase = atomicAdd(&g_nwin[l], __popc(mask));
            wbase = __shfl_sync(mask, wbase, leader);
            int w = wbase + rk;
            if (w < WCAP) g_win[l][w] = ((u64)ord << 32) | (u32)(a - base);
        }
    }
}

// ---- K4: parallel exact rank-select -> g_sel (ascending (~ord, idx)) ----
// grid (WCAP/RBLK, NLEV); each thread ranks ONE element against all n
// via broadcast smem reads. Keys unique -> rank is exact top_k position.
__global__ void __launch_bounds__(RBLK)
k_rank() {
    __shared__ u64 s[WCAP];       // 32 KB (worst case); typical n ~1250
    const int l = blockIdx.y;
    const int t = threadIdx.x;
    int n = g_nwin[l];
    if (n > WCAP) n = WCAP;

    const int e = blockIdx.x * RBLK + t;
    if (blockIdx.x * RBLK >= n) return;       // whole block out of range

    const u64* win = g_win[l];
    for (int i = t; i < n; i += RBLK)
        s[i] = win[i] ^ 0xFFFFFFFF00000000ULL;
    __syncthreads();

    if (e >= n) return;
    const u64 me = s[e];
    int rank = 0;
    int j = 0;
#pragma unroll 4
    for (; j + 8 <= n; j += 8) {
        rank += (s[j] < me) + (s[j + 1] < me) + (s[j + 2] < me) + (s[j + 3] < me)
              + (s[j + 4] < me) + (s[j + 5] < me) + (s[j + 6] < me) + (s[j + 7] < me);
    }
    for (; j < n; j++) rank += (s[j] < me);

    if (rank < TOPK) {
        u32 idx = (u32)(me & 0xFFFFFFFFu);
        if (idx >= (u32)d_len[l]) idx = 0;    // safety (never hit on valid data)
        g_sel[l * TOPK + rank] = idx;
    }
}

// ---- K5: decode + emit, massively parallel (grid 125 x 5, 128 thr) ----
__global__ void __launch_bounds__(128)
k_emit(Ptrs p, float* __restrict__ out) {
    __shared__ float4 bbox[8];
    __shared__ u32 sidx[8];
    const int l = blockIdx.y;
    const int kloc = blockIdx.x * 8;
    const int t = threadIdx.x;

    if (t < 8) {
        u32 idx = g_sel[l * TOPK + kloc + t];
        if (idx >= (u32)d_len[l]) idx = 0;     // safety
        sidx[t] = idx;
        float4 a4 = ((const float4*)p.anc[l])[idx];
        float4 r4 = ((const float4*)p.reg[l])[idx * 2];
        float w = a4.z - a4.x, h = a4.w - a4.y;
        float cx = a4.x + 0.5f * w, cy = a4.y + 0.5f * h;
        float pcx = cx + r4.x * w, pcy = cy + r4.y * h;
        float pw = w * expf(fminf(r4.z, MAXD));
        float ph = h * expf(fminf(r4.w, MAXD));
        bbox[t] = make_float4(pcx - 0.5f * pw, pcy - 0.5f * ph,
                              pcx + 0.5f * pw, pcy + 0.5f * ph);
    }
    __syncthreads();

    const int k = t >> 4;          // 0..7
    const int c = t & 15;
    u32 idx = sidx[k];
    float score = p.cls[l][(size_t)idx * 16 + c];
    float sg = 1.0f / (1.0f + expf(-score));
    float4 b4 = bbox[k];
    float* o = out + ((size_t)(l * TOPK + kloc + k) * CLSN + c) * 6;
    float2* o2 = (float2*)o;
    o2[0] = make_float2(b4.x, b4.y);
    o2[1] = make_float2(b4.z, b4.w);
    o2[2] = make_float2(sg, (float)(c + 1));
}

extern "C" void kernel_launch(void* const* d_in, const int* in_sizes, int n_in,
                              void* d_out, int out_size) {
    (void)in_sizes; (void)n_in; (void)out_size;
    Ptrs p;
    for (int l = 0; l < NLEV; l++) {
        p.anc[l] = (const float*)d_in[3 * l + 0];
        p.cls[l] = (const float*)d_in[3 * l + 1];
        p.reg[l] = (const float*)d_in[3 * l + 2];
    }

    void* hist_ptr = nullptr;
    void* nwin_ptr = nullptr;
    cudaGetSymbolAddress(&hist_ptr, g_hist);
    cudaGetSymbolAddress(&nwin_ptr, g_nwin);
    cudaMemsetAsync(hist_ptr, 0, (size_t)NLEV * HB * sizeof(int), 0);
    cudaMemsetAsync(nwin_ptr, 0, (size_t)NLEV * sizeof(int), 0);

    k_ruler<<<NCHUNK, 512>>>(p);
    k_resolve<<<NLEV, 256>>>();
    k_select<<<NCHUNK, 512>>>();
    dim3 gr(WCAP / RBLK, NLEV);
    k_rank<<<gr, RBLK>>>();
    dim3 ge(TOPK / 8, NLEV);
    k_emit<<<ge, 128>>>(p, (float*)d_out);
}

// round 10
// speedup vs baseline: 4.7969x; 1.0994x over previous
#include <cuda_runtime.h>
#include <stdint.h>

typedef unsigned long long u64;
typedef unsigned int u32;

#define NLEV 5
#define CLSN 16
#define TOPK 1000
#define NTOT 785664
#define KTOT (NLEV * TOPK)
#define HBITS 13
#define HB (1 << HBITS)        /* 8192 bins: ord >> 19 */
#define WCAP 4096
#define CHUNK 1536
#define NCHUNK 512             /* 512*1536 = 786432 >= NTOT */
#define MAXD 4.135166556742356f

__device__ __constant__ int d_off[6] = {0, 589824, 737280, 774144, 783360, 785664};
__device__ __constant__ int d_len[5] = {589824, 147456, 36864, 9216, 2304};

struct Ptrs {
    const float* anc[NLEV];
    const float* cls[NLEV];
    const float* reg[NLEV];
};

// ---------------- scratch (static device globals; no allocation) ----------------
__device__ int g_hist[NLEV * HB];   // zeroed by memset node
__device__ int g_nwin[NLEV];        // zeroed by memset node
__device__ u32 g_ord[NTOT];
__device__ u64 g_win[NLEV][WCAP];
__device__ int g_thr[NLEV];
__device__ u32 g_sel[KTOT];

__device__ __forceinline__ int level_of(int a) {
    int l = 0;
#pragma unroll
    for (int j = 1; j < NLEV; j++) l += (a >= d_off[j]);
    return l;
}

// ---- K1: ruler (max of 16 logits) + PRIVATE shared 13-bit histogram ----
__global__ void __launch_bounds__(512)
k_ruler(Ptrs p) {
    __shared__ u32 h[HB];                     // 32 KB
    const int t = threadIdx.x;
    for (int b = t; b < HB; b += 512) h[b] = 0;
    __syncthreads();

    const int cstart = blockIdx.x * CHUNK;
    const int l = level_of(cstart);
    const int base = d_off[l];
    const int iend = (cstart + CHUNK < NTOT) ? cstart + CHUNK : NTOT;
    const float4* cls4 = (const float4*)p.cls[l];

#pragma unroll
    for (int q = 0; q < 3; q++) {
        int a = cstart + q * 512 + t;
        if (a < iend) {
            int i = a - base;
            float4 va = cls4[i * 4 + 0], vb = cls4[i * 4 + 1];
            float4 vc = cls4[i * 4 + 2], vd = cls4[i * 4 + 3];
            float m = fmaxf(fmaxf(fmaxf(va.x, va.y), fmaxf(va.z, va.w)),
                            fmaxf(fmaxf(vb.x, vb.y), fmaxf(vb.z, vb.w)));
            m = fmaxf(m, fmaxf(fmaxf(vc.x, vc.y), fmaxf(vc.z, vc.w)));
            m = fmaxf(m, fmaxf(fmaxf(vd.x, vd.y), fmaxf(vd.z, vd.w)));
            u32 u = __float_as_uint(m);
            u32 ord = (u & 0x80000000u) ? ~u : (u | 0x80000000u);  // monotonic
            g_ord[a] = ord;
            atomicAdd(&h[ord >> (32 - HBITS)], 1u);
        }
    }
    __syncthreads();

    int* gh = &g_hist[l * HB];
    for (int b = t; b < HB; b += 512) {
        u32 c = h[b];
        if (c) atomicAdd(&gh[b], (int)c);     // <=384 adds per address
    }
}

// ---- K2: per-level threshold bin: largest B with suffix_count(B) >= TOPK ----
__global__ void k_resolve() {
    const int l = blockIdx.x;
    const int t = threadIdx.x;                // 256 threads
    const int CH = HB / 256;                  // 32 bins/thread
    __shared__ int csum[256];
    __shared__ int s_cidx, s_sufnext;
    const int* h = &g_hist[l * HB];

    int base = t * CH, s = 0;
#pragma unroll 4
    for (int j = 0; j < CH; j++) s += h[base + j];
    csum[t] = s;
    __syncthreads();
    for (int off = 1; off < 256; off <<= 1) { // reversed scan -> suffix sums
        int v = csum[t];
        int add = (t + off < 256) ? csum[t + off] : 0;
        __syncthreads();
        csum[t] = v + add;
        __syncthreads();
    }
    if (csum[t] >= TOPK && (t == 255 || csum[t + 1] < TOPK)) {
        s_cidx = t;
        s_sufnext = (t == 255) ? 0 : csum[t + 1];
    }
    __syncthreads();
    if (t == 0) {
        int cbase = s_cidx * CH;
        int suf = s_sufnext, b = cbase + CH - 1;
        for (int j = CH - 1; j >= 0; j--) {
            suf += h[cbase + j];
            b = cbase + j;
            if (suf >= TOPK) break;
        }
        g_thr[l] = b;
    }
}

// ---- K3: collect keys with top13 >= threshold (ballot-aggregated) ----
__global__ void __launch_bounds__(512)
k_select() {
    const int t = threadIdx.x;
    const int cstart = blockIdx.x * CHUNK;
    const int l = level_of(cstart);
    const int base = d_off[l];
    const int iend = (cstart + CHUNK < NTOT) ? cstart + CHUNK : NTOT;
    const u32 thr = (u32)g_thr[l];
    const int lane = t & 31;

#pragma unroll
    for (int q = 0; q < 3; q++) {
        int a = cstart + q * 512 + t;
        bool win = false;
        u32 ord = 0;
        if (a < iend) {
            ord = g_ord[a];
            win = (ord >> (32 - HBITS)) >= thr;
        }
        unsigned act = __activemask();
        unsigned mask = __ballot_sync(act, win);
        if (win) {
            int leader = __ffs(mask) - 1;
            int rk = __popc(mask & ((1u << lane) - 1));
            int wbase = 0;
            if (lane == leader) wbase = atomicAdd(&g_nwin[l], __popc(mask));
            wbase = __shfl_sync(mask, wbase, leader);
            int w = wbase + rk;
            if (w < WCAP) g_win[l][w] = ((u64)ord << 32) | (u32)(a - base);
        }
    }
}

// ---- K4: warp-per-element exact rank-select -> g_sel ----
// grid (WCAP/8, NLEV), block 256 = 8 warps. Warp w ranks element
// e = blockIdx.x*8 + w: 32 lanes scan strided slices, __reduce_add combine.
// Keys (~ord, idx) unique -> rank is the exact jax top_k position.
__global__ void __launch_bounds__(256)
k_rank() {
    __shared__ u64 s[WCAP];       // 32 KB worst case; typical n ~1250
    const int l = blockIdx.y;
    const int t = threadIdx.x;
    const int warp = t >> 5;
    const int lane = t & 31;
    int n = g_nwin[l];
    if (n > WCAP) n = WCAP;
    if (blockIdx.x * 8 >= n) return;          // whole block out of range

    const u64* win = g_win[l];
    for (int i = t; i < n; i += 256)
        s[i] = win[i] ^ 0xFFFFFFFF00000000ULL;   // ascending (~ord, idx)
    __syncthreads();

    const int e = blockIdx.x * 8 + warp;
    if (e >= n) return;
    const u64 me = s[e];
    int cnt = 0;
    for (int j = lane; j < n; j += 32)        // conflict-free strided LDS
        cnt += (s[j] < me);
    int rank = __reduce_add_sync(0xFFFFFFFFu, cnt);

    if (lane == 0 && rank < TOPK) {
        u32 idx = (u32)(me & 0xFFFFFFFFu);
        if (idx >= (u32)d_len[l]) idx = 0;    // safety (never hit on valid data)
        g_sel[l * TOPK + rank] = idx;
    }
}

// ---- K5: decode + emit, massively parallel (grid 125 x 5, 128 thr) ----
__global__ void __launch_bounds__(128)
k_emit(Ptrs p, float* __restrict__ out) {
    __shared__ float4 bbox[8];
    __shared__ u32 sidx[8];
    const int l = blockIdx.y;
    const int kloc = blockIdx.x * 8;
    const int t = threadIdx.x;

    if (t < 8) {
        u32 idx = g_sel[l * TOPK + kloc + t];
        if (idx >= (u32)d_len[l]) idx = 0;     // safety
        sidx[t] = idx;
        float4 a4 = ((const float4*)p.anc[l])[idx];
        float4 r4 = ((const float4*)p.reg[l])[idx * 2];
        float w = a4.z - a4.x, h = a4.w - a4.y;
        float cx = a4.x + 0.5f * w, cy = a4.y + 0.5f * h;
        float pcx = cx + r4.x * w, pcy = cy + r4.y * h;
        float pw = w * expf(fminf(r4.z, MAXD));
        float ph = h * expf(fminf(r4.w, MAXD));
        bbox[t] = make_float4(pcx - 0.5f * pw, pcy - 0.5f * ph,
                              pcx + 0.5f * pw, pcy + 0.5f * ph);
    }
    __syncthreads();

    const int k = t >> 4;          // 0..7
    const int c = t & 15;
    u32 idx = sidx[k];
    float score = p.cls[l][(size_t)idx * 16 + c];
    float sg = 1.0f / (1.0f + expf(-score));
    float4 b4 = bbox[k];
    float* o = out + ((size_t)(l * TOPK + kloc + k) * CLSN + c) * 6;
    float2* o2 = (float2*)o;
    o2[0] = make_float2(b4.x, b4.y);
    o2[1] = make_float2(b4.z, b4.w);
    o2[2] = make_float2(sg, (float)(c + 1));
}

extern "C" void kernel_launch(void* const* d_in, const int* in_sizes, int n_in,
                              void* d_out, int out_size) {
    (void)in_sizes; (void)n_in; (void)out_size;
    Ptrs p;
    for (int l = 0; l < NLEV; l++) {
        p.anc[l] = (const float*)d_in[3 * l + 0];
        p.cls[l] = (const float*)d_in[3 * l + 1];
        p.reg[l] = (const float*)d_in[3 * l + 2];
    }

    void* hist_ptr = nullptr;
    void* nwin_ptr = nullptr;
    cudaGetSymbolAddress(&hist_ptr, g_hist);
    cudaGetSymbolAddress(&nwin_ptr, g_nwin);
    cudaMemsetAsync(hist_ptr, 0, (size_t)NLEV * HB * sizeof(int), 0);
    cudaMemsetAsync(nwin_ptr, 0, (size_t)NLEV * sizeof(int), 0);

    k_ruler<<<NCHUNK, 512>>>(p);
    k_resolve<<<NLEV, 256>>>();
    k_select<<<NCHUNK, 512>>>();
    dim3 gr(WCAP / 8, NLEV);
    k_rank<<<gr, 256>>>();
    dim3 ge(TOPK / 8, NLEV);
    k_emit<<<ge, 128>>>(p, (float*)d_out);
}

// round 11
// speedup vs baseline: 5.4432x; 1.1347x over previous
#include <cuda_runtime.h>
#include <stdint.h>

typedef unsigned long long u64;
typedef unsigned int u32;

#define NLEV 5
#define CLSN 16
#define TOPK 1000
#define NTOT 785664
#define KTOT (NLEV * TOPK)
#define HBITS 13
#define HB (1 << HBITS)        /* 8192 bins: ord >> 19 */
#define WCAP 4096
#define CHUNK 1536
#define NCHUNK 512             /* 512*1536 = 786432 >= NTOT */
#define MAXD 4.135166556742356f

__device__ __constant__ int d_off[6] = {0, 589824, 737280, 774144, 783360, 785664};
__device__ __constant__ int d_len[5] = {589824, 147456, 36864, 9216, 2304};

struct Ptrs {
    const float* anc[NLEV];
    const float* cls[NLEV];
    const float* reg[NLEV];
};

// ---------------- scratch (static device globals; no allocation) ----------------
__device__ int g_hist[NLEV * HB];   // zeroed by memset node
__device__ int g_nwin[NLEV];        // zeroed inside k_resolve
__device__ u32 g_ord[NTOT];
__device__ u64 g_win[NLEV][WCAP];
__device__ int g_thr[NLEV];
__device__ u32 g_sel[KTOT];

__device__ __forceinline__ int level_of(int a) {
    int l = 0;
#pragma unroll
    for (int j = 1; j < NLEV; j++) l += (a >= d_off[j]);
    return l;
}

// ---- K1: ruler (max of 16 logits) + PRIVATE shared 13-bit histogram ----
__global__ void __launch_bounds__(512)
k_ruler(Ptrs p) {
    __shared__ u32 h[HB];                     // 32 KB
    const int t = threadIdx.x;
    for (int b = t; b < HB; b += 512) h[b] = 0;
    __syncthreads();

    const int cstart = blockIdx.x * CHUNK;
    const int l = level_of(cstart);
    const int base = d_off[l];
    const int iend = (cstart + CHUNK < NTOT) ? cstart + CHUNK : NTOT;
    const float4* cls4 = (const float4*)p.cls[l];

#pragma unroll
    for (int q = 0; q < 3; q++) {
        int a = cstart + q * 512 + t;
        if (a < iend) {
            int i = a - base;
            float4 va = cls4[i * 4 + 0], vb = cls4[i * 4 + 1];
            float4 vc = cls4[i * 4 + 2], vd = cls4[i * 4 + 3];
            float m = fmaxf(fmaxf(fmaxf(va.x, va.y), fmaxf(va.z, va.w)),
                            fmaxf(fmaxf(vb.x, vb.y), fmaxf(vb.z, vb.w)));
            m = fmaxf(m, fmaxf(fmaxf(vc.x, vc.y), fmaxf(vc.z, vc.w)));
            m = fmaxf(m, fmaxf(fmaxf(vd.x, vd.y), fmaxf(vd.z, vd.w)));
            u32 u = __float_as_uint(m);
            u32 ord = (u & 0x80000000u) ? ~u : (u | 0x80000000u);  // monotonic
            g_ord[a] = ord;
            atomicAdd(&h[ord >> (32 - HBITS)], 1u);
        }
    }
    __syncthreads();

    int* gh = &g_hist[l * HB];
    for (int b = t; b < HB; b += 512) {
        u32 c = h[b];
        if (c) atomicAdd(&gh[b], (int)c);     // <=384 adds per address
    }
}

// ---- K2: per-level threshold bin + zero g_nwin ----
__global__ void k_resolve() {
    const int l = blockIdx.x;
    const int t = threadIdx.x;                // 256 threads
    const int CH = HB / 256;                  // 32 bins/thread
    __shared__ int csum[256];
    __shared__ int s_cidx, s_sufnext;
    const int* h = &g_hist[l * HB];

    if (t == 0) g_nwin[l] = 0;                // consumed only by k_select (later)

    int base = t * CH, s = 0;
#pragma unroll 4
    for (int j = 0; j < CH; j++) s += h[base + j];
    csum[t] = s;
    __syncthreads();
    for (int off = 1; off < 256; off <<= 1) { // reversed scan -> suffix sums
        int v = csum[t];
        int add = (t + off < 256) ? csum[t + off] : 0;
        __syncthreads();
        csum[t] = v + add;
        __syncthreads();
    }
    if (csum[t] >= TOPK && (t == 255 || csum[t + 1] < TOPK)) {
        s_cidx = t;
        s_sufnext = (t == 255) ? 0 : csum[t + 1];
    }
    __syncthreads();
    if (t == 0) {
        int cbase = s_cidx * CH;
        int suf = s_sufnext, b = cbase + CH - 1;
        for (int j = CH - 1; j >= 0; j--) {
            suf += h[cbase + j];
            b = cbase + j;
            if (suf >= TOPK) break;
        }
        g_thr[l] = b;
    }
}

// ---- K3: collect keys with top13 >= threshold (ballot-aggregated) ----
__global__ void __launch_bounds__(512)
k_select() {
    const int t = threadIdx.x;
    const int cstart = blockIdx.x * CHUNK;
    const int l = level_of(cstart);
    const int base = d_off[l];
    const int iend = (cstart + CHUNK < NTOT) ? cstart + CHUNK : NTOT;
    const u32 thr = (u32)g_thr[l];
    const int lane = t & 31;

#pragma unroll
    for (int q = 0; q < 3; q++) {
        int a = cstart + q * 512 + t;
        bool win = false;
        u32 ord = 0;
        if (a < iend) {
            ord = g_ord[a];
            win = (ord >> (32 - HBITS)) >= thr;
        }
        unsigned act = __activemask();
        unsigned mask = __ballot_sync(act, win);
        if (win) {
            int leader = __ffs(mask) - 1;
            int rk = __popc(mask & ((1u << lane) - 1));
            int wbase = 0;
            if (lane == leader) wbase = atomicAdd(&g_nwin[l], __popc(mask));
            wbase = __shfl_sync(mask, wbase, leader);
            int w = wbase + rk;
            if (w < WCAP) g_win[l][w] = ((u64)ord << 32) | (u32)(a - base);
        }
    }
}

// ---- K4: exact rank-select, 8 elements per warp per scan pass ----
// grid (WCAP/64, NLEV), block 256 = 8 warps -> 64 elements per block.
// Each lane loads s[j] ONCE and compares vs 8 register pivots.
// Keys (~ord, idx) unique -> rank == exact jax top_k position.
__global__ void __launch_bounds__(256)
k_rank() {
    __shared__ u64 s[WCAP];       // 32 KB worst case; typical n ~1250
    const int l = blockIdx.y;
    const int t = threadIdx.x;
    const int warp = t >> 5;
    const int lane = t & 31;
    int n = g_nwin[l];
    if (n > WCAP) n = WCAP;
    if (blockIdx.x * 64 >= n) return;         // whole block out of range

    const u64* win = g_win[l];
    for (int i = t; i < n; i += 256)
        s[i] = win[i] ^ 0xFFFFFFFF00000000ULL;   // ascending (~ord, idx)
    __syncthreads();

    const int ebase = blockIdx.x * 64 + warp * 8;
    if (ebase >= n) return;

    u64 me[8];
    int cnt[8] = {0, 0, 0, 0, 0, 0, 0, 0};
#pragma unroll
    for (int q = 0; q < 8; q++)
        me[q] = (ebase + q < n) ? s[ebase + q] : ~0ULL;

    for (int j = lane; j < n; j += 32) {      // conflict-free strided LDS
        u64 v = s[j];
#pragma unroll
        for (int q = 0; q < 8; q++) cnt[q] += (v < me[q]);
    }

#pragma unroll
    for (int q = 0; q < 8; q++) {
        int rank = __reduce_add_sync(0xFFFFFFFFu, cnt[q]);
        if (lane == 0 && ebase + q < n && rank < TOPK) {
            u32 idx = (u32)(me[q] & 0xFFFFFFFFu);
            if (idx >= (u32)d_len[l]) idx = 0;   // safety
            g_sel[l * TOPK + rank] = idx;
        }
    }
}

// ---- K5: decode + emit, massively parallel (grid 125 x 5, 128 thr) ----
__global__ void __launch_bounds__(128)
k_emit(Ptrs p, float* __restrict__ out) {
    __shared__ float4 bbox[8];
    __shared__ u32 sidx[8];
    const int l = blockIdx.y;
    const int kloc = blockIdx.x * 8;
    const int t = threadIdx.x;

    if (t < 8) {
        u32 idx = g_sel[l * TOPK + kloc + t];
        if (idx >= (u32)d_len[l]) idx = 0;     // safety
        sidx[t] = idx;
        float4 a4 = ((const float4*)p.anc[l])[idx];
        float4 r4 = ((const float4*)p.reg[l])[idx * 2];
        float w = a4.z - a4.x, h = a4.w - a4.y;
        float cx = a4.x + 0.5f * w, cy = a4.y + 0.5f * h;
        float pcx = cx + r4.x * w, pcy = cy + r4.y * h;
        float pw = w * expf(fminf(r4.z, MAXD));
        float ph = h * expf(fminf(r4.w, MAXD));
        bbox[t] = make_float4(pcx - 0.5f * pw, pcy - 0.5f * ph,
                              pcx + 0.5f * pw, pcy + 0.5f * ph);
    }
    __syncthreads();

    const int k = t >> 4;          // 0..7
    const int c = t & 15;
    u32 idx = sidx[k];
    float score = p.cls[l][(size_t)idx * 16 + c];
    float sg = 1.0f / (1.0f + expf(-score));
    float4 b4 = bbox[k];
    float* o = out + ((size_t)(l * TOPK + kloc + k) * CLSN + c) * 6;
    float2* o2 = (float2*)o;
    o2[0] = make_float2(b4.x, b4.y);
    o2[1] = make_float2(b4.z, b4.w);
    o2[2] = make_float2(sg, (float)(c + 1));
}

extern "C" void kernel_launch(void* const* d_in, const int* in_sizes, int n_in,
                              void* d_out, int out_size) {
    (void)in_sizes; (void)n_in; (void)out_size;
    Ptrs p;
    for (int l = 0; l < NLEV; l++) {
        p.anc[l] = (const float*)d_in[3 * l + 0];
        p.cls[l] = (const float*)d_in[3 * l + 1];
        p.reg[l] = (const float*)d_in[3 * l + 2];
    }

    void* hist_ptr = nullptr;
    cudaGetSymbolAddress(&hist_ptr, g_hist);
    cudaMemsetAsync(hist_ptr, 0, (size_t)NLEV * HB * sizeof(int), 0);

    k_ruler<<<NCHUNK, 512>>>(p);
    k_resolve<<<NLEV, 256>>>();
    k_select<<<NCHUNK, 512>>>();
    dim3 gr(WCAP / 64, NLEV);
    k_rank<<<gr, 256>>>();
    dim3 ge(TOPK / 8, NLEV);
    k_emit<<<ge, 128>>>(p, (float*)d_out);
}